// round 1
// baseline (speedup 1.0000x reference)
#include <cuda_runtime.h>
#include <cstdint>
#include <cstddef>

// Problem dims
#define T_STEPS 512
#define BATCH   256
#define NF      160
#define H       128
#define GC      512   // 4*H gate columns

// Recurrent kernel org: 32 teams x 4 CTAs. Team owns 8 batch rows.
// CTA owns 32 hidden units (=> 128 gate cols) of BOTH layers.
#define TEAMS 32
#define ROWS_PER_TEAM 8
#define UNITS_PER_CTA 32
#define KP 132   // padded row stride (floats) for weight slices in smem
#define HP 132   // padded row stride for h / gate buffers in smem

// -------- global scratch (static __device__, allocation-free) --------
__device__ float    g_xpre[(size_t)T_STEPS * BATCH * GC];       // 256 MB
__device__ float    g_h1s[TEAMS][ROWS_PER_TEAM][H];
__device__ float    g_h2s[TEAMS][ROWS_PER_TEAM][H];
__device__ unsigned g_barc[TEAMS * 2 * 32];                     // stride-32 counters

// ---------------------------------------------------------------
__global__ void init_kernel() {
    int i = threadIdx.x;
    for (; i < TEAMS * 2 * 32; i += blockDim.x) g_barc[i] = 0u;
}

// ---------------------------------------------------------------
// Precompute: Xpre[t][b][gc] = sum_k x[b][t][k] * Wih0[gc][k] + bih0[gc]+bhh0[gc]
// grid: (512 t, 4 b-tiles of 64, 8 gc-tiles of 64), 256 threads.
#define PRE_SMEM (2 * 64 * 164 * 4)
__global__ __launch_bounds__(256) void precompute_kernel(
    const float* __restrict__ x,
    const float* __restrict__ Wih0,
    const float* __restrict__ bih0,
    const float* __restrict__ bhh0)
{
    extern __shared__ float sm[];
    float* xs = sm;              // [64][164]
    float* ws = sm + 64 * 164;   // [64][164]

    const int t   = blockIdx.x;
    const int b0  = blockIdx.y * 64;
    const int gc0 = blockIdx.z * 64;
    const int tid = threadIdx.x;

    for (int idx = tid; idx < 64 * 40; idx += 256) {
        int row = idx / 40;
        int q   = (idx % 40) * 4;
        *(float4*)&xs[row * 164 + q] =
            *(const float4*)&x[((size_t)(b0 + row) * T_STEPS + t) * NF + q];
        *(float4*)&ws[row * 164 + q] =
            *(const float4*)&Wih0[(size_t)(gc0 + row) * NF + q];
    }
    __syncthreads();

    const int tx = tid & 15;   // col group (cols tx, tx+16, tx+32, tx+48)
    const int ty = tid >> 4;   // row group (rows ty, ty+16, ty+32, ty+48)

    float acc[4][4] = {};
#pragma unroll 4
    for (int k = 0; k < NF; k += 4) {
        float4 av[4], bv[4];
#pragma unroll
        for (int i = 0; i < 4; i++) av[i] = *(const float4*)&xs[(ty + 16 * i) * 164 + k];
#pragma unroll
        for (int j = 0; j < 4; j++) bv[j] = *(const float4*)&ws[(tx + 16 * j) * 164 + k];
#pragma unroll
        for (int i = 0; i < 4; i++)
#pragma unroll
            for (int j = 0; j < 4; j++)
                acc[i][j] += av[i].x * bv[j].x + av[i].y * bv[j].y +
                             av[i].z * bv[j].z + av[i].w * bv[j].w;
    }

#pragma unroll
    for (int i = 0; i < 4; i++) {
        int b = b0 + ty + 16 * i;
#pragma unroll
        for (int j = 0; j < 4; j++) {
            int gc = gc0 + tx + 16 * j;
            float bias = __ldg(&bih0[gc]) + __ldg(&bhh0[gc]);
            g_xpre[((size_t)t * BATCH + b) * GC + gc] = acc[i][j] + bias;
        }
    }
}

// ---------------------------------------------------------------
__device__ __forceinline__ float sigm(float v)  { return 1.0f / (1.0f + __expf(-v)); }
__device__ __forceinline__ float tanhx(float v) { return 1.0f - 2.0f / (__expf(2.0f * v) + 1.0f); }

__device__ __forceinline__ unsigned ld_acq(const unsigned* p) {
    unsigned v;
    asm volatile("ld.global.acquire.gpu.u32 %0, [%1];" : "=r"(v) : "l"(p) : "memory");
    return v;
}

// 8x128x128 fp32 GEMM fragment: lane accumulates rows r0..r0+3 of column jc.
__device__ __forceinline__ void gemm_acc(
    const float* __restrict__ W, const float* __restrict__ Hm,
    int jc, int r0, float& a0, float& a1, float& a2, float& a3)
{
    const float* wp  = &W[jc * KP];
    const float* hp0 = &Hm[(r0 + 0) * HP];
    const float* hp1 = &Hm[(r0 + 1) * HP];
    const float* hp2 = &Hm[(r0 + 2) * HP];
    const float* hp3 = &Hm[(r0 + 3) * HP];
#pragma unroll 8
    for (int k = 0; k < H; k += 4) {
        float4 wv = *(const float4*)&wp[k];
        float4 h0 = *(const float4*)&hp0[k];
        float4 h1 = *(const float4*)&hp1[k];
        float4 h2 = *(const float4*)&hp2[k];
        float4 h3 = *(const float4*)&hp3[k];
        a0 += wv.x * h0.x + wv.y * h0.y + wv.z * h0.z + wv.w * h0.w;
        a1 += wv.x * h1.x + wv.y * h1.y + wv.z * h1.z + wv.w * h1.w;
        a2 += wv.x * h2.x + wv.y * h2.y + wv.z * h2.z + wv.w * h2.w;
        a3 += wv.x * h3.x + wv.y * h3.y + wv.z * h3.z + wv.w * h3.w;
    }
}

#define REC_SMEM ((3 * 128 * KP + 3 * 8 * HP + 128) * 4)

__global__ __launch_bounds__(256, 1) void lstm_recurrent_kernel(
    const float* __restrict__ h0,
    const float* __restrict__ c0,
    const float* __restrict__ Whh0,
    const float* __restrict__ Wih1,
    const float* __restrict__ Whh1,
    const float* __restrict__ bih1,
    const float* __restrict__ bhh1,
    float* __restrict__ out)
{
    extern __shared__ float sm[];
    float* w0  = sm;                  // [128][KP]  W_hh0 slice (row = local gate col)
    float* w1i = w0  + 128 * KP;      // [128][KP]  W_ih1 slice
    float* w1h = w1i + 128 * KP;      // [128][KP]  W_hh1 slice
    float* h1s = w1h + 128 * KP;      // [8][HP]
    float* h2s = h1s + 8 * HP;        // [8][HP]
    float* gs  = h2s + 8 * HP;        // [8][HP] gate staging
    float* b1s = gs  + 8 * HP;        // [128] layer-1 bias slice

    const int tid   = threadIdx.x;
    const int bid   = blockIdx.x;
    const int team  = bid >> 2;
    const int cslot = bid & 3;
    const int brow0 = team * ROWS_PER_TEAM;
    const int ubase = cslot * UNITS_PER_CTA;

    // --- load resident weight slices (local col j -> global gate row) ---
    for (int idx = tid; idx < 128 * 32; idx += 256) {
        int j = idx >> 5;
        int q = (idx & 31) * 4;
        int grow = (j >> 5) * H + ubase + (j & 31);   // gate*128 + unit
        *(float4*)&w0 [j * KP + q] = *(const float4*)&Whh0[(size_t)grow * H + q];
        *(float4*)&w1i[j * KP + q] = *(const float4*)&Wih1[(size_t)grow * H + q];
        *(float4*)&w1h[j * KP + q] = *(const float4*)&Whh1[(size_t)grow * H + q];
    }
    for (int j = tid; j < 128; j += 256) {
        int grow = (j >> 5) * H + ubase + (j & 31);
        b1s[j] = bih1[grow] + bhh1[grow];
    }
    // --- init h from h0 (full 128 per row, replicated) ---
    for (int idx = tid; idx < 8 * 32; idx += 256) {
        int r = idx >> 5;
        int q = (idx & 31) * 4;
        *(float4*)&h1s[r * HP + q] = *(const float4*)&h0[((size_t)(brow0 + r)) * H + q];
        *(float4*)&h2s[r * HP + q] = *(const float4*)&h0[((size_t)(BATCH + brow0 + r)) * H + q];
    }
    // --- c state: one (row, unit) per pointwise thread, kept in registers ---
    const int pr = tid >> 5;   // 0..7
    const int pu = tid & 31;   // 0..31
    float c1 = c0[((size_t)(brow0 + pr)) * H + ubase + pu];
    float c2 = c0[((size_t)(BATCH + brow0 + pr)) * H + ubase + pu];
    __syncthreads();

    // GEMM lane mapping: warp w covers cols [16w,16w+16); lane pair shares col.
    const int warp = tid >> 5;
    const int lane = tid & 31;
    const int jc = warp * 16 + (lane >> 1);
    const int r0 = (lane & 1) * 4;

    unsigned* ctrA = &g_barc[(team * 2 + 0) * 32];
    unsigned* ctrB = &g_barc[(team * 2 + 1) * 32];

    for (int t = 0; t < T_STEPS; t++) {
        // ================= Phase A: layer-0 recurrent ==================
        float a0 = 0.f, a1 = 0.f, a2 = 0.f, a3 = 0.f;
        gemm_acc(w0, h1s, jc, r0, a0, a1, a2, a3);
        gs[(r0 + 0) * HP + jc] = a0;
        gs[(r0 + 1) * HP + jc] = a1;
        gs[(r0 + 2) * HP + jc] = a2;
        gs[(r0 + 3) * HP + jc] = a3;
        __syncthreads();

        {
            const float* xp = &g_xpre[((size_t)t * BATCH + brow0 + pr) * GC];
            float gi = gs[pr * HP +       pu] + __ldg(&xp[0 * H + ubase + pu]);
            float gf = gs[pr * HP +  32 + pu] + __ldg(&xp[1 * H + ubase + pu]);
            float gg = gs[pr * HP +  64 + pu] + __ldg(&xp[2 * H + ubase + pu]);
            float go = gs[pr * HP +  96 + pu] + __ldg(&xp[3 * H + ubase + pu]);
            float iv = sigm(gi), fv = sigm(gf), gv = tanhx(gg), ov = sigm(go);
            c1 = fv * c1 + iv * gv;
            float h1v = ov * tanhx(c1);
            g_h1s[team][pr][ubase + pu] = h1v;
        }
        __threadfence();
        __syncthreads();
        if (tid == 0) {
            atomicAdd(ctrA, 1u);
            unsigned target = 4u * (unsigned)(t + 1);
            while (ld_acq(ctrA) < target) { }
            __threadfence();
        }
        __syncthreads();
        {   // gather full h1_t into smem
            int r = tid >> 5, q = (tid & 31) * 4;
            *(float4*)&h1s[r * HP + q] = __ldcg((const float4*)&g_h1s[team][r][q]);
        }
        __syncthreads();

        // ================= Phase B: layer-1 =================
        a0 = 0.f; a1 = 0.f; a2 = 0.f; a3 = 0.f;
        gemm_acc(w1i, h1s, jc, r0, a0, a1, a2, a3);
        gemm_acc(w1h, h2s, jc, r0, a0, a1, a2, a3);
        __syncthreads();   // everyone done reading h2s before gs overwrite is fine; gs reuse needs sync
        gs[(r0 + 0) * HP + jc] = a0;
        gs[(r0 + 1) * HP + jc] = a1;
        gs[(r0 + 2) * HP + jc] = a2;
        gs[(r0 + 3) * HP + jc] = a3;
        __syncthreads();

        {
            float gi = gs[pr * HP +       pu] + b1s[      pu];
            float gf = gs[pr * HP +  32 + pu] + b1s[ 32 + pu];
            float gg = gs[pr * HP +  64 + pu] + b1s[ 64 + pu];
            float go = gs[pr * HP +  96 + pu] + b1s[ 96 + pu];
            float iv = sigm(gi), fv = sigm(gf), gv = tanhx(gg), ov = sigm(go);
            c2 = fv * c2 + iv * gv;
            float h2v = ov * tanhx(c2);
            g_h2s[team][pr][ubase + pu] = h2v;
            if (t == T_STEPS - 1)
                out[(size_t)(brow0 + pr) * H + ubase + pu] = h2v;
        }
        __threadfence();
        __syncthreads();
        if (tid == 0) {
            atomicAdd(ctrB, 1u);
            unsigned target = 4u * (unsigned)(t + 1);
            while (ld_acq(ctrB) < target) { }
            __threadfence();
        }
        __syncthreads();
        {   // gather full h2_t into smem
            int r = tid >> 5, q = (tid & 31) * 4;
            *(float4*)&h2s[r * HP + q] = __ldcg((const float4*)&g_h2s[team][r][q]);
        }
        __syncthreads();
    }
}

// ---------------------------------------------------------------
extern "C" void kernel_launch(void* const* d_in, const int* in_sizes, int n_in,
                              void* d_out, int out_size)
{
    const float* x    = (const float*)d_in[0];
    const float* h0   = (const float*)d_in[1];
    const float* c0   = (const float*)d_in[2];
    const float* Wih0 = (const float*)d_in[3];
    const float* Whh0 = (const float*)d_in[4];
    const float* bih0 = (const float*)d_in[5];
    const float* bhh0 = (const float*)d_in[6];
    const float* Wih1 = (const float*)d_in[7];
    const float* Whh1 = (const float*)d_in[8];
    const float* bih1 = (const float*)d_in[9];
    const float* bhh1 = (const float*)d_in[10];
    float* out = (float*)d_out;

    cudaFuncSetAttribute(precompute_kernel,
                         cudaFuncAttributeMaxDynamicSharedMemorySize, PRE_SMEM);
    cudaFuncSetAttribute(lstm_recurrent_kernel,
                         cudaFuncAttributeMaxDynamicSharedMemorySize, REC_SMEM);

    init_kernel<<<1, 256>>>();

    dim3 pgrid(T_STEPS, 4, 8);
    precompute_kernel<<<pgrid, 256, PRE_SMEM>>>(x, Wih0, bih0, bhh0);

    lstm_recurrent_kernel<<<TEAMS * 4, 256, REC_SMEM>>>(
        h0, c0, Whh0, Wih1, Whh1, bih1, bhh1, out);
}

// round 3
// speedup vs baseline: 1.4527x; 1.4527x over previous
#include <cuda_runtime.h>
#include <cstdint>
#include <cstddef>

// Problem dims
#define T_STEPS 512
#define BATCH   256
#define NF      160
#define H       128
#define GC      512   // 4*H gate columns

// Recurrent org: 32 clusters (teams) x 4 CTAs. Team owns 8 batch rows.
// CTA owns 32 hidden units (=> 128 gate cols) of BOTH layers.
#define TEAMS 32
#define ROWS_PER_TEAM 8
#define UNITS_PER_CTA 32
#define KP 132   // padded row stride (floats) for weight slices in smem
#define HP 132   // padded row stride for h / gate buffers in smem

// -------- global scratch (static __device__, allocation-free) --------
__device__ float g_xpre[(size_t)T_STEPS * BATCH * GC];       // 256 MB

// ---------------- f32x2 helpers ----------------
__device__ __forceinline__ void ffma2(unsigned long long& d,
                                      unsigned long long a,
                                      unsigned long long b) {
    asm("fma.rn.f32x2 %0, %1, %2, %0;" : "+l"(d) : "l"(a), "l"(b));
}
__device__ __forceinline__ float hsum2(unsigned long long v) {
    unsigned lo, hi;
    asm("mov.b64 {%0,%1}, %2;" : "=r"(lo), "=r"(hi) : "l"(v));
    return __uint_as_float(lo) + __uint_as_float(hi);
}

// ---------------- cluster helpers ----------------
__device__ __forceinline__ void cluster_sync_() {
    asm volatile("barrier.cluster.arrive.aligned;" ::: "memory");
    asm volatile("barrier.cluster.wait.aligned;" ::: "memory");
}
__device__ __forceinline__ unsigned ctarank_() {
    unsigned r;
    asm("mov.u32 %0, %%cluster_ctarank;" : "=r"(r));
    return r;
}
__device__ __forceinline__ void st_peer_f32(uint32_t local_smem_addr, int rank, float v) {
    uint32_t ra;
    asm("mapa.shared::cluster.u32 %0, %1, %2;" : "=r"(ra) : "r"(local_smem_addr), "r"(rank));
    asm volatile("st.shared::cluster.f32 [%0], %1;" :: "r"(ra), "f"(v) : "memory");
}

// ---------------------------------------------------------------
// Precompute: Xpre[t][b][gc] = sum_k x[b][t][k] * Wih0[gc][k] + bih0[gc]+bhh0[gc]
// grid: (512 t, 4 b-tiles of 64, 8 gc-tiles of 64), 256 threads.
#define PRE_SMEM (2 * 64 * 164 * 4)
__global__ __launch_bounds__(256) void precompute_kernel(
    const float* __restrict__ x,
    const float* __restrict__ Wih0,
    const float* __restrict__ bih0,
    const float* __restrict__ bhh0)
{
    extern __shared__ float sm[];
    float* xs = sm;              // [64][164]
    float* ws = sm + 64 * 164;   // [64][164]

    const int t   = blockIdx.x;
    const int b0  = blockIdx.y * 64;
    const int gc0 = blockIdx.z * 64;
    const int tid = threadIdx.x;

    for (int idx = tid; idx < 64 * 40; idx += 256) {
        int row = idx / 40;
        int q   = (idx % 40) * 4;
        *(float4*)&xs[row * 164 + q] =
            *(const float4*)&x[((size_t)(b0 + row) * T_STEPS + t) * NF + q];
        *(float4*)&ws[row * 164 + q] =
            *(const float4*)&Wih0[(size_t)(gc0 + row) * NF + q];
    }
    __syncthreads();

    const int tx = tid & 15;   // col group (cols tx, tx+16, tx+32, tx+48)
    const int ty = tid >> 4;   // row group (rows ty, ty+16, ty+32, ty+48)

    unsigned long long acc[4][4];
#pragma unroll
    for (int i = 0; i < 4; i++)
#pragma unroll
        for (int j = 0; j < 4; j++) acc[i][j] = 0ull;

#pragma unroll 4
    for (int k = 0; k < NF; k += 4) {
        ulonglong2 av[4], bv[4];
#pragma unroll
        for (int i = 0; i < 4; i++) av[i] = *(const ulonglong2*)&xs[(ty + 16 * i) * 164 + k];
#pragma unroll
        for (int j = 0; j < 4; j++) bv[j] = *(const ulonglong2*)&ws[(tx + 16 * j) * 164 + k];
#pragma unroll
        for (int i = 0; i < 4; i++)
#pragma unroll
            for (int j = 0; j < 4; j++) {
                ffma2(acc[i][j], av[i].x, bv[j].x);
                ffma2(acc[i][j], av[i].y, bv[j].y);
            }
    }

#pragma unroll
    for (int i = 0; i < 4; i++) {
        int b = b0 + ty + 16 * i;
#pragma unroll
        for (int j = 0; j < 4; j++) {
            int gc = gc0 + tx + 16 * j;
            float bias = __ldg(&bih0[gc]) + __ldg(&bhh0[gc]);
            g_xpre[((size_t)t * BATCH + b) * GC + gc] = hsum2(acc[i][j]) + bias;
        }
    }
}

// ---------------------------------------------------------------
__device__ __forceinline__ float sigm(float v)  { return 1.0f / (1.0f + __expf(-v)); }
__device__ __forceinline__ float tanhx(float v) { return 1.0f - 2.0f / (__expf(2.0f * v) + 1.0f); }

// 8x128x128 fp32 GEMM fragment: lane accumulates rows r0..r0+3 of column jc.
__device__ __forceinline__ void gemm_acc2(
    const float* __restrict__ W, const float* __restrict__ Hm,
    int jc, int r0, unsigned long long acc[4])
{
    const float* wp = &W[jc * KP];
    const float* hp = &Hm[r0 * HP];
#pragma unroll 8
    for (int k = 0; k < H; k += 4) {
        ulonglong2 wv = *(const ulonglong2*)&wp[k];
#pragma unroll
        for (int i = 0; i < 4; i++) {
            ulonglong2 hv = *(const ulonglong2*)&hp[i * HP + k];
            ffma2(acc[i], wv.x, hv.x);
            ffma2(acc[i], wv.y, hv.y);
        }
    }
}

#define REC_SMEM ((3 * 128 * KP + 4 * 8 * HP + 8 * HP + 128) * 4)

__global__ __launch_bounds__(256, 1) __cluster_dims__(4, 1, 1)
void lstm_recurrent_kernel(
    const float* __restrict__ h0,
    const float* __restrict__ c0,
    const float* __restrict__ Whh0,
    const float* __restrict__ Wih1,
    const float* __restrict__ Whh1,
    const float* __restrict__ bih1,
    const float* __restrict__ bhh1,
    float* __restrict__ out)
{
    extern __shared__ float sm[];
    float* w0  = sm;                  // [128][KP]  W_hh0 slice (row = local gate col)
    float* w1i = w0  + 128 * KP;      // [128][KP]  W_ih1 slice
    float* w1h = w1i + 128 * KP;      // [128][KP]  W_hh1 slice
    float* h1b = w1h + 128 * KP;      // [2][8][HP] double-buffered h1
    float* h2b = h1b + 2 * 8 * HP;    // [2][8][HP] double-buffered h2
    float* gs  = h2b + 2 * 8 * HP;    // [8][HP] gate staging
    float* b1s = gs  + 8 * HP;        // [128] layer-1 bias slice

    const int tid   = threadIdx.x;
    const int team  = blockIdx.x >> 2;
    const int rank  = (int)ctarank_();
    const int brow0 = team * ROWS_PER_TEAM;
    const int ubase = rank * UNITS_PER_CTA;

    // --- load resident weight slices (local col j -> global gate row) ---
    for (int idx = tid; idx < 128 * 32; idx += 256) {
        int j = idx >> 5;
        int q = (idx & 31) * 4;
        int grow = (j >> 5) * H + ubase + (j & 31);   // gate*128 + unit
        *(float4*)&w0 [j * KP + q] = *(const float4*)&Whh0[(size_t)grow * H + q];
        *(float4*)&w1i[j * KP + q] = *(const float4*)&Wih1[(size_t)grow * H + q];
        *(float4*)&w1h[j * KP + q] = *(const float4*)&Whh1[(size_t)grow * H + q];
    }
    for (int j = tid; j < 128; j += 256) {
        int grow = (j >> 5) * H + ubase + (j & 31);
        b1s[j] = bih1[grow] + bhh1[grow];
    }
    // --- init h buffers (buffer 0) from h0 (full 128 per row) ---
    for (int idx = tid; idx < 8 * 32; idx += 256) {
        int r = idx >> 5;
        int q = (idx & 31) * 4;
        *(float4*)&h1b[r * HP + q] = *(const float4*)&h0[((size_t)(brow0 + r)) * H + q];
        *(float4*)&h2b[r * HP + q] = *(const float4*)&h0[((size_t)(BATCH + brow0 + r)) * H + q];
    }
    // --- c state: one (row, unit) per pointwise thread, kept in registers ---
    const int pr = tid >> 5;   // 0..7
    const int pu = tid & 31;   // 0..31
    float c1 = c0[((size_t)(brow0 + pr)) * H + ubase + pu];
    float c2 = c0[((size_t)(BATCH + brow0 + pr)) * H + ubase + pu];
    __syncthreads();
    // hoist layer-1 bias into registers (constant per thread)
    const float bb0 = b1s[      pu];
    const float bb1 = b1s[ 32 + pu];
    const float bb2 = b1s[ 64 + pu];
    const float bb3 = b1s[ 96 + pu];
    cluster_sync_();           // all CTAs initialized before any peer traffic

    // GEMM lane mapping: warp w covers cols [16w,16w+16); lane pair shares col.
    const int warp = tid >> 5;
    const int lane = tid & 31;
    const int jc = warp * 16 + (lane >> 1);
    const int r0 = (lane & 1) * 4;

    // smem u32 addresses of this thread's pointwise h element in each buffer
    const uint32_t h1a0 = (uint32_t)__cvta_generic_to_shared(&h1b[pr * HP + ubase + pu]);
    const uint32_t h1a1 = (uint32_t)__cvta_generic_to_shared(&h1b[8 * HP + pr * HP + ubase + pu]);
    const uint32_t h2a0 = (uint32_t)__cvta_generic_to_shared(&h2b[pr * HP + ubase + pu]);
    const uint32_t h2a1 = (uint32_t)__cvta_generic_to_shared(&h2b[8 * HP + pr * HP + ubase + pu]);

    for (int t = 0; t < T_STEPS; t++) {
        const int p = t & 1;
        float* h1cur = h1b + p * 8 * HP;
        float* h1nxt = h1b + (p ^ 1) * 8 * HP;
        float* h2cur = h2b + p * 8 * HP;

        // prefetch this thread's xpre gates (hidden behind gemmA)
        const float* xp = &g_xpre[((size_t)t * BATCH + brow0 + pr) * GC + ubase + pu];
        float xg0 = __ldg(&xp[0 * H]);
        float xg1 = __ldg(&xp[1 * H]);
        float xg2 = __ldg(&xp[2 * H]);
        float xg3 = __ldg(&xp[3 * H]);

        // ================= Phase A: layer-0 recurrent ==================
        unsigned long long acc[4] = {0ull, 0ull, 0ull, 0ull};
        gemm_acc2(w0, h1cur, jc, r0, acc);
#pragma unroll
        for (int i = 0; i < 4; i++) gs[(r0 + i) * HP + jc] = hsum2(acc[i]);
        __syncthreads();

        {
            float gi = gs[pr * HP +       pu] + xg0;
            float gf = gs[pr * HP +  32 + pu] + xg1;
            float gg = gs[pr * HP +  64 + pu] + xg2;
            float go = gs[pr * HP +  96 + pu] + xg3;
            float iv = sigm(gi), fv = sigm(gf), gv = tanhx(gg), ov = sigm(go);
            c1 = fv * c1 + iv * gv;
            float h1v = ov * tanhx(c1);
            uint32_t a = p ? h1a0 : h1a1;   // write NEXT buffer in all 4 CTAs
#pragma unroll
            for (int rk = 0; rk < 4; rk++) st_peer_f32(a, rk, h1v);
        }
        // Single cluster sync per step: makes h1_t visible for phase B now,
        // and (by the same barrier next iteration) h2_t visible for phase B
        // of t+1. Double buffering covers all anti-dependencies.
        cluster_sync_();

        // ================= Phase B: layer-1 =================
        unsigned long long accb[4] = {0ull, 0ull, 0ull, 0ull};
        gemm_acc2(w1i, h1nxt, jc, r0, accb);
        gemm_acc2(w1h, h2cur, jc, r0, accb);
        __syncthreads();   // gs reads of phase A done before overwrite
#pragma unroll
        for (int i = 0; i < 4; i++) gs[(r0 + i) * HP + jc] = hsum2(accb[i]);
        __syncthreads();

        {
            float gi = gs[pr * HP +       pu] + bb0;
            float gf = gs[pr * HP +  32 + pu] + bb1;
            float gg = gs[pr * HP +  64 + pu] + bb2;
            float go = gs[pr * HP +  96 + pu] + bb3;
            float iv = sigm(gi), fv = sigm(gf), gv = tanhx(gg), ov = sigm(go);
            c2 = fv * c2 + iv * gv;
            float h2v = ov * tanhx(c2);
            uint32_t a = p ? h2a0 : h2a1;
#pragma unroll
            for (int rk = 0; rk < 4; rk++) st_peer_f32(a, rk, h2v);
            if (t == T_STEPS - 1)
                out[(size_t)(brow0 + pr) * H + ubase + pu] = h2v;
        }
        // no second cluster sync: next iteration's sync covers h2_t
    }
    cluster_sync_();   // drain in-flight peer stores before exit
}

// ---------------------------------------------------------------
extern "C" void kernel_launch(void* const* d_in, const int* in_sizes, int n_in,
                              void* d_out, int out_size)
{
    const float* x    = (const float*)d_in[0];
    const float* h0   = (const float*)d_in[1];
    const float* c0   = (const float*)d_in[2];
    const float* Wih0 = (const float*)d_in[3];
    const float* Whh0 = (const float*)d_in[4];
    const float* bih0 = (const float*)d_in[5];
    const float* bhh0 = (const float*)d_in[6];
    const float* Wih1 = (const float*)d_in[7];
    const float* Whh1 = (const float*)d_in[8];
    const float* bih1 = (const float*)d_in[9];
    const float* bhh1 = (const float*)d_in[10];
    float* out = (float*)d_out;

    cudaFuncSetAttribute(precompute_kernel,
                         cudaFuncAttributeMaxDynamicSharedMemorySize, PRE_SMEM);
    cudaFuncSetAttribute(lstm_recurrent_kernel,
                         cudaFuncAttributeMaxDynamicSharedMemorySize, REC_SMEM);

    dim3 pgrid(T_STEPS, 4, 8);
    precompute_kernel<<<pgrid, 256, PRE_SMEM>>>(x, Wih0, bih0, bhh0);

    lstm_recurrent_kernel<<<TEAMS * 4, 256, REC_SMEM>>>(
        h0, c0, Whh0, Wih1, Whh1, bih1, bhh1, out);
}